// round 5
// baseline (speedup 1.0000x reference)
#include <cuda_runtime.h>
#include <cuda_bf16.h>
#include <float.h>
#include <math.h>

// Problem shape (fixed by reference setup_inputs)
#define B_   16
#define C_   256
#define H_   128
#define W_   128
#define HW_  (H_ * W_)           // 16384
#define HW4_ (HW_ / 4)           // 4096 float4 columns per image

// Scratch: feat [B, 2, H, W]  (avg then max)
__device__ float g_feat[B_ * 2 * HW_];
// Row-ready flags and consumed-counters, one per (image, row).
// Zero at module load; the consumed-count protocol in the conv kernel resets
// them to zero every launch, so graph replays start clean.
__device__ int g_flag[B_ * H_];
__device__ int g_cnt [B_ * H_];

// ---------------------------------------------------------------------------
// Kernel 1 (producer): channel-wise mean + max over C=256.
// Block (b, h-row): 256 thr = 32 float4 columns x 8 channel-splits of 32 ch.
// Pure streaming block: triggers PDL at start, publishes a row flag at end.
// ---------------------------------------------------------------------------
__global__ __launch_bounds__(256) void reduce_mean_max_kernel(
    const float* __restrict__ x)
{
    // Let the dependent conv grid begin launching as soon as every producer
    // CTA is resident (trigger-at-start). Consumers sync via row flags.
    cudaTriggerProgrammaticLaunchCompletion();

    __shared__ float4 s_sum[256];
    __shared__ float4 s_max[256];

    const int tid = threadIdx.x;
    const int col = tid & 31;                  // hw4 column within row
    const int cs  = tid >> 5;                  // channel split 0..7

    const int blk = blockIdx.x;                // 0..2047 == b*128 + h
    const int b   = blk >> 7;
    const int hw4 = ((blk & 127) << 5) + col;  // row h, 32 float4 per row

    const float4* xb = reinterpret_cast<const float4*>(x)
                     + (size_t)b * C_ * HW4_ + (size_t)(cs * 32) * HW4_ + hw4;

    float4 s = make_float4(0.f, 0.f, 0.f, 0.f);
    float4 m = make_float4(-FLT_MAX, -FLT_MAX, -FLT_MAX, -FLT_MAX);

    #pragma unroll 8
    for (int c = 0; c < 32; ++c) {
        float4 v = __ldcs(xb + (size_t)c * HW4_);
        s.x += v.x; s.y += v.y; s.z += v.z; s.w += v.w;
        m.x = fmaxf(m.x, v.x); m.y = fmaxf(m.y, v.y);
        m.z = fmaxf(m.z, v.z); m.w = fmaxf(m.w, v.w);
    }

    s_sum[tid] = s;
    s_max[tid] = m;
    __syncthreads();

    if (tid < 32) {
        #pragma unroll
        for (int k = 1; k < 8; ++k) {
            float4 ps = s_sum[tid + k * 32];
            float4 pm = s_max[tid + k * 32];
            s.x += ps.x; s.y += ps.y; s.z += ps.z; s.w += ps.w;
            m.x = fmaxf(m.x, pm.x); m.y = fmaxf(m.y, pm.y);
            m.z = fmaxf(m.z, pm.z); m.w = fmaxf(m.w, pm.w);
        }
        const float inv = 1.0f / (float)C_;
        float4 a = make_float4(s.x * inv, s.y * inv, s.z * inv, s.w * inv);

        float4* fa = reinterpret_cast<float4*>(g_feat)
                   + (size_t)b * 2 * HW4_ + hw4;
        fa[0]    = a;   // channel 0: avg
        fa[HW4_] = m;   // channel 1: max

        __threadfence();   // make feat row visible device-wide before flag
    }
    __syncthreads();
    if (tid == 0) atomicExch(&g_flag[blk], 1);
}

// ---------------------------------------------------------------------------
// Kernel 2 (consumer): 3x3 conv (2 in ch, pad 1, no bias) + sigmoid.
// Block = one output row (b, h), 128 threads = one pixel each.
// Spins on the 2-3 producer row flags it needs, so it overlaps the producer
// grid's drain instead of waiting for full completion.
// ---------------------------------------------------------------------------
__global__ __launch_bounds__(128) void conv_sigmoid_kernel(
    const float* __restrict__ conv_w,   // [1,2,3,3] OIHW
    float* __restrict__ out)            // [B,1,H,W]
{
    const int tid = threadIdx.x;        // w = 0..127
    const int blk = blockIdx.x;         // b*128 + h
    const int b   = blk >> 7;
    const int h   = blk & 127;

    // Prologue before the wait: weights into registers.
    float wk[18];
    #pragma unroll
    for (int i = 0; i < 18; ++i) wk[i] = __ldg(conv_w + i);

    // Wait for the 3 producer rows this block needs.
    if (tid == 0) {
        #pragma unroll
        for (int dr = -1; dr <= 1; ++dr) {
            const int rh = h + dr;
            if (rh < 0 || rh >= H_) continue;
            while (atomicAdd(&g_flag[b * H_ + rh], 0) == 0) __nanosleep(64);
        }
        __threadfence();
    }
    __syncthreads();

    const float* fb = g_feat + (size_t)b * 2 * HW_;
    const int w = tid;

    float acc = 0.f;
    #pragma unroll
    for (int r = 0; r < 3; ++r) {
        const int hh = h + r - 1;
        if (hh < 0 || hh >= H_) continue;
        const float* r0 = fb + hh * W_;   // avg channel row
        const float* r1 = r0 + HW_;       // max channel row
        #pragma unroll
        for (int kw = 0; kw < 3; ++kw) {
            const int ww = w + kw - 1;
            if (ww < 0 || ww >= W_) continue;
            acc = fmaf(r0[ww], wk[r * 3 + kw],     acc);
            acc = fmaf(r1[ww], wk[9 + r * 3 + kw], acc);
        }
    }

    out[(size_t)b * HW_ + h * W_ + w] = 1.0f / (1.0f + __expf(-acc));

    // Consumed-count bookkeeping: last consumer of each row resets its flag,
    // leaving all flags/counters zero for the next (graph-replayed) launch.
    __syncthreads();
    if (tid == 0) {
        #pragma unroll
        for (int dr = -1; dr <= 1; ++dr) {
            const int rh = h + dr;
            if (rh < 0 || rh >= H_) continue;
            const int r = b * H_ + rh;
            const int target = (rh == 0 || rh == H_ - 1) ? 2 : 3;
            if (atomicAdd(&g_cnt[r], 1) == target - 1) {
                atomicExch(&g_cnt[r], 0);
                atomicExch(&g_flag[r], 0);
            }
        }
    }
}

// ---------------------------------------------------------------------------
extern "C" void kernel_launch(void* const* d_in, const int* in_sizes, int n_in,
                              void* d_out, int out_size)
{
    const float* x      = (const float*)d_in[0];   // [16,256,128,128] f32
    const float* conv_w = (const float*)d_in[1];   // [1,2,3,3] f32
    float*       out    = (float*)d_out;           // [16,1,128,128] f32

    // Producer: 2048 blocks x 256 threads
    reduce_mean_max_kernel<<<B_ * H_, 256>>>(x);

    // Consumer: 2048 blocks x 128 threads, PDL early launch + row-flag sync
    cudaLaunchConfig_t cfg = {};
    cfg.gridDim  = dim3(B_ * H_, 1, 1);
    cfg.blockDim = dim3(128, 1, 1);
    cfg.dynamicSmemBytes = 0;
    cfg.stream = 0;

    cudaLaunchAttribute attrs[1];
    attrs[0].id = cudaLaunchAttributeProgrammaticStreamSerialization;
    attrs[0].val.programmaticStreamSerializationAllowed = 1;
    cfg.attrs = attrs;
    cfg.numAttrs = 1;

    cudaLaunchKernelEx(&cfg, conv_sigmoid_kernel, conv_w, out);
}

// round 6
// speedup vs baseline: 1.0899x; 1.0899x over previous
#include <cuda_runtime.h>
#include <cuda_bf16.h>
#include <float.h>
#include <math.h>

// Problem shape (fixed by reference setup_inputs)
#define B_   16
#define C_   256
#define H_   128
#define W_   128
#define HW_  (H_ * W_)           // 16384
#define HW4_ (HW_ / 4)           // 4096 float4 columns per image

// Scratch: feat [B, 2, H, W]  (avg then max)
__device__ float g_feat[B_ * 2 * HW_];

// ---------------------------------------------------------------------------
// Kernel 1: channel-wise mean + max over C=256.
// Block = half a spatial row: (16 float4 cols) x (16 channel-splits of 16 ch).
// 4096 blocks of 16 loads/thread -> fine work quanta so the ragged last wave
// costs ~1 half-block instead of a full 24us block (R3's 13.5% util loss).
// ---------------------------------------------------------------------------
__global__ __launch_bounds__(256) void reduce_mean_max_kernel(
    const float* __restrict__ x)
{
    cudaTriggerProgrammaticLaunchCompletion();

    __shared__ float4 s_sum[256];
    __shared__ float4 s_max[256];

    const int tid  = threadIdx.x;
    const int col  = tid & 15;                 // float4 column within half-row
    const int cs   = tid >> 4;                 // channel split 0..15

    const int blk    = blockIdx.x;             // 0..4095
    const int row_id = blk >> 1;               // 0..2047 == b*128 + h
    const int half   = blk & 1;
    const int b      = row_id >> 7;
    const int h      = row_id & 127;
    const int hw4    = (h << 5) + (half << 4) + col;

    const float4* xb = reinterpret_cast<const float4*>(x)
                     + (size_t)b * C_ * HW4_ + (size_t)(cs * 16) * HW4_ + hw4;

    float4 s = make_float4(0.f, 0.f, 0.f, 0.f);
    float4 m = make_float4(-FLT_MAX, -FLT_MAX, -FLT_MAX, -FLT_MAX);

    #pragma unroll
    for (int c = 0; c < 16; ++c) {
        float4 v = __ldcs(xb + (size_t)c * HW4_);
        s.x += v.x; s.y += v.y; s.z += v.z; s.w += v.w;
        m.x = fmaxf(m.x, v.x); m.y = fmaxf(m.y, v.y);
        m.z = fmaxf(m.z, v.z); m.w = fmaxf(m.w, v.w);
    }

    s_sum[tid] = s;
    s_max[tid] = m;
    __syncthreads();

    if (tid < 16) {
        #pragma unroll
        for (int k = 1; k < 16; ++k) {
            float4 ps = s_sum[tid + k * 16];
            float4 pm = s_max[tid + k * 16];
            s.x += ps.x; s.y += ps.y; s.z += ps.z; s.w += ps.w;
            m.x = fmaxf(m.x, pm.x); m.y = fmaxf(m.y, pm.y);
            m.z = fmaxf(m.z, pm.z); m.w = fmaxf(m.w, pm.w);
        }
        const float inv = 1.0f / (float)C_;
        float4 a = make_float4(s.x * inv, s.y * inv, s.z * inv, s.w * inv);

        float4* fa = reinterpret_cast<float4*>(g_feat)
                   + (size_t)b * 2 * HW4_ + hw4;
        fa[0]    = a;   // channel 0: avg
        fa[HW4_] = m;   // channel 1: max
    }
}

// ---------------------------------------------------------------------------
// Kernel 2: 3x3 conv (2 in ch, 1 out ch, pad 1, no bias) + sigmoid.
// One thread per output pixel (fastest measured config). PDL: weights load in
// the prologue, grid dependency sync, then conv against L2-hot g_feat.
// ---------------------------------------------------------------------------
__global__ __launch_bounds__(256) void conv_sigmoid_kernel(
    const float* __restrict__ conv_w,   // [1,2,3,3] OIHW
    float* __restrict__ out)            // [B,1,H,W]
{
    const int idx = blockIdx.x * blockDim.x + threadIdx.x;  // 0 .. B*HW-1
    const int b  = idx >> 14;           // / HW_
    const int hw = idx & (HW_ - 1);
    const int h  = hw >> 7;             // / W_
    const int w  = hw & (W_ - 1);

    // Prologue (overlaps producer drain): weights into registers.
    float wk[18];
    #pragma unroll
    for (int i = 0; i < 18; ++i) wk[i] = __ldg(conv_w + i);

    cudaGridDependencySynchronize();

    const float* f0 = g_feat + (size_t)b * 2 * HW_;   // avg channel
    const float* f1 = f0 + HW_;                       // max channel

    float acc = 0.f;
    #pragma unroll
    for (int kh = 0; kh < 3; ++kh) {
        const int hh = h + kh - 1;
        if (hh < 0 || hh >= H_) continue;
        #pragma unroll
        for (int kw = 0; kw < 3; ++kw) {
            const int ww = w + kw - 1;
            if (ww < 0 || ww >= W_) continue;
            const int off = hh * W_ + ww;
            acc = fmaf(f0[off], wk[kh * 3 + kw], acc);
            acc = fmaf(f1[off], wk[9 + kh * 3 + kw], acc);
        }
    }

    out[idx] = 1.0f / (1.0f + __expf(-acc));
}

// ---------------------------------------------------------------------------
extern "C" void kernel_launch(void* const* d_in, const int* in_sizes, int n_in,
                              void* d_out, int out_size)
{
    const float* x      = (const float*)d_in[0];   // [16,256,128,128] f32
    const float* conv_w = (const float*)d_in[1];   // [1,2,3,3] f32
    float*       out    = (float*)d_out;           // [16,1,128,128] f32

    // Kernel 1: 4096 blocks x 256 threads
    reduce_mean_max_kernel<<<4096, 256>>>(x);

    // Kernel 2: 1024 blocks x 256 threads, PDL-overlapped launch
    cudaLaunchConfig_t cfg = {};
    cfg.gridDim  = dim3((B_ * HW_) / 256, 1, 1);
    cfg.blockDim = dim3(256, 1, 1);
    cfg.dynamicSmemBytes = 0;
    cfg.stream = 0;

    cudaLaunchAttribute attrs[1];
    attrs[0].id = cudaLaunchAttributeProgrammaticStreamSerialization;
    attrs[0].val.programmaticStreamSerializationAllowed = 1;
    cfg.attrs = attrs;
    cfg.numAttrs = 1;

    cudaLaunchKernelEx(&cfg, conv_sigmoid_kernel, conv_w, out);
}